// round 14
// baseline (speedup 1.0000x reference)
#include <cuda_runtime.h>
#include <cstddef>
#include <cstdint>

#define BB   8
#define NF   64
#define FIN  192
#define FH   128
#define LATD 512
#define PT   61824
#define P0   16384   // 128*128

// ---------------- scratch (device globals; no allocation) ----------------
__device__ float g_out [BB*NF *P0];
__device__ float g_perc[BB*2*NF*P0];  // dx,dy only (identity read from g_out)
__device__ float g_h1  [BB*FH *P0];
__device__ float g_h2  [BB*FH *P0];
__device__ float g_full[BB*NF *P0];
__device__ float g_dyn [BB*PT];
__device__ float g_wAT [BB*FIN*FH];   // [192][128] per sample (w_in^T)
__device__ float g_wMT [BB*FH*FH];    // [128][128] per sample (w_mid^T)
__device__ float g_wCDT[BB*320*NF];   // [320][64]: rows 0..127 w_out^T, 128..319 w_sk^T
__device__ float g_bA  [BB*FH];
__device__ float g_bM  [BB*FH];
__device__ float g_bCD [BB*NF];
__device__ float g_hvec[BB*NF];
__device__ float g_wRB [2*NF*NF];     // transposed inrb_w0, inrb_w1 (shared across batch)

__device__ __forceinline__ float lrelu(float x){ return x > 0.0f ? x : 0.2f*x; }
__device__ __forceinline__ float4 lrelu4(float4 v){
    return make_float4(lrelu(v.x), lrelu(v.y), lrelu(v.z), lrelu(v.w));
}
__device__ __forceinline__ void fma2(unsigned long long &d, unsigned long long a, unsigned long long b) {
    asm("fma.rn.f32x2 %0, %1, %2, %0;" : "+l"(d) : "l"(a), "l"(b));
}
__device__ __forceinline__ float2 unpack2(unsigned long long v) {
    float2 r; asm("mov.b64 {%0,%1}, %2;" : "=f"(r.x), "=f"(r.y) : "l"(v)); return r;
}
__device__ __forceinline__ unsigned long long pack2(float lo, float hi) {
    unsigned long long r; asm("mov.b64 %0, {%1,%2};" : "=l"(r) : "f"(lo), "f"(hi)); return r;
}

// ---------------- transpose static resblock weights ----------------
__global__ void k_trw(const float* __restrict__ w0, const float* __restrict__ w1)
{
    const int i = blockIdx.x*256 + threadIdx.x;   // 8192
    if (i < 4096) { int k = i >> 6, o = i & 63; g_wRB[i] = w0[o*64 + k]; }
    else { int j = i - 4096; int k = j >> 6, o = j & 63; g_wRB[i] = w1[o*64 + k]; }
}

// ------- hypernet: dyn = inj_lat @ hyp_w + hyp_b (float4, batch-split grid) -----
__global__ void k_hyper(const float* __restrict__ inj, const float* __restrict__ hw,
                        const float* __restrict__ hb)
{
    __shared__ float s_inj[4*LATD];
    const int tid = threadIdx.x;  // 128
    const int b0 = blockIdx.y * 4;
    for (int e = tid; e < 4*LATD; e += 128) s_inj[e] = inj[b0*LATD + e];
    __syncthreads();
    const int j4 = (blockIdx.x*128 + tid) * 4;
    if (j4 >= PT) return;
    float4 acc[4];
    #pragma unroll
    for (int b = 0; b < 4; ++b) acc[b] = make_float4(0.f,0.f,0.f,0.f);
    for (int k = 0; k < LATD; ++k) {
        float4 w = *(const float4*)&hw[(size_t)k*PT + j4];
        #pragma unroll
        for (int b = 0; b < 4; ++b) {
            float s = s_inj[b*LATD+k];
            acc[b].x += s*w.x; acc[b].y += s*w.y;
            acc[b].z += s*w.z; acc[b].w += s*w.w;
        }
    }
    float4 bb = *(const float4*)&hb[j4];
    #pragma unroll
    for (int b = 0; b < 4; ++b) {
        float4 r = make_float4(acc[b].x+bb.x, acc[b].y+bb.y, acc[b].z+bb.z, acc[b].w+bb.w);
        *(float4*)&g_dyn[(size_t)(b0+b)*PT + j4] = r;
    }
}

// ---------------- transpose dyn params into GEMM-friendly layout ----------------
__global__ void k_tr()
{
    const int b = blockIdx.y;
    int i = blockIdx.x*256 + threadIdx.x;
    const float* d = g_dyn + (size_t)b*PT;
    if (i < FIN*FH) { int k = i/FH, o = i%FH; g_wAT[(size_t)b*FIN*FH + i] = d[o*FIN + k]; return; }
    i -= FIN*FH;
    if (i < FH*FH)  { int k = i/FH, o = i%FH; g_wMT[(size_t)b*FH*FH + i] = d[24704 + o*FH + k]; return; }
    i -= FH*FH;
    if (i < 320*NF) { int k = i/NF, o = i%NF;
        g_wCDT[(size_t)b*320*NF + i] = (k < FH) ? d[41216 + o*FH + k]
                                                : d[49472 + o*FIN + (k-FH)];
        return; }
    i -= 320*NF;
    if (i < FH) { g_bA[b*FH+i] = d[24576+i]; return; }
    i -= FH;
    if (i < FH) { g_bM[b*FH+i] = d[41088+i]; return; }
    i -= FH;
    if (i < NF) { g_bCD[b*NF+i] = d[49408+i] + d[61760+i]; return; }
}

// ------- sin_sobel derivatives only: g_out -> g_perc [2NF ch], 4 px/thread -------
// used once, at H=128 (resblock output); later iterations fuse sobel into down
__global__ void k_sobel4(int H, int lgH)
{
    const int P = H*H;
    const int idx = blockIdx.x*256 + threadIdx.x;
    if (idx >= BB*NF*(P>>2)) return;
    const int q  = idx & ((P>>2)-1);
    const int c  = (idx >> (2*lgH-2)) & 63;
    const int b  = idx >> (2*lgH+4);
    const int p4 = q << 2;
    const int y  = p4 >> lgH, x0 = p4 & (H-1);
    const float* src = g_out + (size_t)(b*NF+c)*P;

    float am[6], ac[6], ap[6];
    {
        float4 v = *(const float4*)&src[p4];
        ac[0] = (x0 > 0)     ? src[p4-1] : 0.f;
        ac[1] = v.x; ac[2] = v.y; ac[3] = v.z; ac[4] = v.w;
        ac[5] = (x0+4 < H)   ? src[p4+4] : 0.f;
    }
    if (y > 0) {
        int base = (y-1) << lgH;
        float4 v = *(const float4*)&src[base + x0];
        am[0] = (x0 > 0)   ? src[base+x0-1] : 0.f;
        am[1] = v.x; am[2] = v.y; am[3] = v.z; am[4] = v.w;
        am[5] = (x0+4 < H) ? src[base+x0+4] : 0.f;
    } else { am[0]=am[1]=am[2]=am[3]=am[4]=am[5]=0.f; }
    if (y < H-1) {
        int base = (y+1) << lgH;
        float4 v = *(const float4*)&src[base + x0];
        ap[0] = (x0 > 0)   ? src[base+x0-1] : 0.f;
        ap[1] = v.x; ap[2] = v.y; ap[3] = v.z; ap[4] = v.w;
        ap[5] = (x0+4 < H) ? src[base+x0+4] : 0.f;
    } else { ap[0]=ap[1]=ap[2]=ap[3]=ap[4]=ap[5]=0.f; }

    float sx[4], sy[4];
    #pragma unroll
    for (int i = 0; i < 4; ++i) {
        float m00 = am[i], m01 = am[i+1], m02 = am[i+2];
        float m10 = ac[i],               m12 = ac[i+2];
        float m20 = ap[i], m21 = ap[i+1], m22 = ap[i+2];
        sx[i] = (m00 - m02 + 2.f*(m10 - m12) + m20 - m22) * 0.125f;
        sy[i] = (m00 + 2.f*m01 + m02 - m20 - 2.f*m21 - m22) * 0.125f;
    }
    float* dst = g_perc + (size_t)b*(2*NF)*P;
    *(float4*)&dst[(size_t) c    *P + p4] = make_float4(sx[0],sx[1],sx[2],sx[3]);
    *(float4*)&dst[(size_t)(NF+c)*P + p4] = make_float4(sy[0],sy[1],sy[2],sy[3]);
}

// ---- fused input path: y = conv1x1(x); out = y + 0.1*(lrelu(lrelu(y)@w0+b0)@w1+b1)
// BM=256, BN=64, K=64 twice; x tile and h1 tile live in smem; y recomputed in epilogue.
__global__ void __launch_bounds__(256, 1) k_inres(
    const float* __restrict__ X, const float* __restrict__ in_w,
    const float* __restrict__ in_b, const float* __restrict__ Wrb,
    const float* __restrict__ B0, const float* __restrict__ B1,
    float* __restrict__ OUT, float* __restrict__ EMB)
{
    constexpr int BM = 256, BN = 64, BK = 32, TMC = 32;
    extern __shared__ float smem[];
    float (*As)[BK][BM] = (float(*)[BK][BM])smem;                 // 64 KB
    float (*Ws)[BK][BN] = (float(*)[BK][BN])(smem + 2*BK*BM);     // 16 KB
    float* s_x  = smem + 2*BK*BM + 2*BK*BN;                       // 3*256 floats
    float4* s_cw = (float4*)(s_x + 3*BM);                         // 64 float4

    const int b  = blockIdx.y;
    const int m0 = blockIdx.x * BM;
    const float* xb = X + (size_t)b*3*P0 + m0;
    const int tid = threadIdx.x;
    const int tm = tid % TMC, tn = tid / TMC;

    // stage x tile (3 x 256) and conv coefficients
    if (tid < 192) {
        int ch = tid >> 6, i = tid & 63;
        *(float4*)&s_x[ch*BM + i*4] = *(const float4*)(xb + (size_t)ch*P0 + i*4);
    }
    if (tid < 64) s_cw[tid] = make_float4(in_w[tid*3], in_w[tid*3+1], in_w[tid*3+2], in_b[tid]);
    __syncthreads();

    // stage lrelu(y) (K=64) and W0
    #pragma unroll
    for (int l = 0; l < 16; ++l) {
        int f = tid + l*256;
        int kk = f >> 6;
        int mv = (f & 63) << 2;
        float4 cw = s_cw[kk];
        float4 a = *(const float4*)&s_x[mv];
        float4 c = *(const float4*)&s_x[BM + mv];
        float4 d = *(const float4*)&s_x[2*BM + mv];
        float4 y;
        y.x = cw.w + cw.x*a.x + cw.y*c.x + cw.z*d.x;
        y.y = cw.w + cw.x*a.y + cw.y*c.y + cw.z*d.y;
        y.z = cw.w + cw.x*a.z + cw.y*c.z + cw.z*d.z;
        y.w = cw.w + cw.x*a.w + cw.y*c.w + cw.z*d.w;
        *(float4*)&As[kk>>5][kk&31][mv] = lrelu4(y);
    }
    #pragma unroll
    for (int l = 0; l < 4; ++l) {
        int f = tid + l*256;
        int kk = f >> 4;
        int nv = (f & 15) << 2;
        *(float4*)&Ws[kk>>5][kk&31][nv] = *(const float4*)(Wrb + kk*BN + nv);
    }
    __syncthreads();

    unsigned long long acc[2][2][4][2];
    #pragma unroll
    for (int af=0; af<2; ++af)
        #pragma unroll
        for (int wf=0; wf<2; ++wf)
            #pragma unroll
            for (int j=0;j<4;++j){ acc[af][wf][j][0]=0ULL; acc[af][wf][j][1]=0ULL; }

    #pragma unroll
    for (int t = 0; t < 2; ++t)
        #pragma unroll
        for (int kc = 0; kc < BK; ++kc) {
            ulonglong2 aA = *(const ulonglong2*)&As[t][kc][tm*4];
            ulonglong2 aB = *(const ulonglong2*)&As[t][kc][128 + tm*4];
            float4 wa = *(const float4*)&Ws[t][kc][tn*4];
            float4 wb = *(const float4*)&Ws[t][kc][32 + tn*4];
            unsigned long long wd[2][4];
            wd[0][0]=pack2(wa.x,wa.x); wd[0][1]=pack2(wa.y,wa.y);
            wd[0][2]=pack2(wa.z,wa.z); wd[0][3]=pack2(wa.w,wa.w);
            wd[1][0]=pack2(wb.x,wb.x); wd[1][1]=pack2(wb.y,wb.y);
            wd[1][2]=pack2(wb.z,wb.z); wd[1][3]=pack2(wb.w,wb.w);
            #pragma unroll
            for (int wf = 0; wf < 2; ++wf)
                #pragma unroll
                for (int j = 0; j < 4; ++j) {
                    fma2(acc[0][wf][j][0], wd[wf][j], aA.x);
                    fma2(acc[0][wf][j][1], wd[wf][j], aA.y);
                    fma2(acc[1][wf][j][0], wd[wf][j], aB.x);
                    fma2(acc[1][wf][j][1], wd[wf][j], aB.y);
                }
        }
    __syncthreads();   // all As/Ws reads done

    // h1 = lrelu(acc + b0) -> As (k = n layout); stage W1
    #pragma unroll
    for (int wf = 0; wf < 2; ++wf)
        #pragma unroll
        for (int j = 0; j < 4; ++j) {
            const int n = wf*32 + tn*4 + j;
            const float bv = B0[n];
            #pragma unroll
            for (int af = 0; af < 2; ++af) {
                float2 p0 = unpack2(acc[af][wf][j][0]);
                float2 p1 = unpack2(acc[af][wf][j][1]);
                *(float4*)&As[n>>5][n&31][af*128 + tm*4] =
                    make_float4(lrelu(p0.x+bv), lrelu(p0.y+bv),
                                lrelu(p1.x+bv), lrelu(p1.y+bv));
                acc[af][wf][j][0] = 0ULL; acc[af][wf][j][1] = 0ULL;
            }
        }
    #pragma unroll
    for (int l = 0; l < 4; ++l) {
        int f = tid + l*256;
        int kk = f >> 4;
        int nv = (f & 15) << 2;
        *(float4*)&Ws[kk>>5][kk&31][nv] = *(const float4*)(Wrb + NF*NF + kk*BN + nv);
    }
    __syncthreads();

    #pragma unroll
    for (int t = 0; t < 2; ++t)
        #pragma unroll
        for (int kc = 0; kc < BK; ++kc) {
            ulonglong2 aA = *(const ulonglong2*)&As[t][kc][tm*4];
            ulonglong2 aB = *(const ulonglong2*)&As[t][kc][128 + tm*4];
            float4 wa = *(const float4*)&Ws[t][kc][tn*4];
            float4 wb = *(const float4*)&Ws[t][kc][32 + tn*4];
            unsigned long long wd[2][4];
            wd[0][0]=pack2(wa.x,wa.x); wd[0][1]=pack2(wa.y,wa.y);
            wd[0][2]=pack2(wa.z,wa.z); wd[0][3]=pack2(wa.w,wa.w);
            wd[1][0]=pack2(wb.x,wb.x); wd[1][1]=pack2(wb.y,wb.y);
            wd[1][2]=pack2(wb.z,wb.z); wd[1][3]=pack2(wb.w,wb.w);
            #pragma unroll
            for (int wf = 0; wf < 2; ++wf)
                #pragma unroll
                for (int j = 0; j < 4; ++j) {
                    fma2(acc[0][wf][j][0], wd[wf][j], aA.x);
                    fma2(acc[0][wf][j][1], wd[wf][j], aA.y);
                    fma2(acc[1][wf][j][0], wd[wf][j], aB.x);
                    fma2(acc[1][wf][j][1], wd[wf][j], aB.y);
                }
        }

    // epilogue: out = y + 0.1*(acc + b1), dual-store OUT/EMB (y recomputed from x)
    #pragma unroll
    for (int af = 0; af < 2; ++af) {
        const int ml = af*128 + tm*4;   // local m
        const int m  = m0 + ml;
        float4 a = *(const float4*)&s_x[ml];
        float4 c = *(const float4*)&s_x[BM + ml];
        float4 d = *(const float4*)&s_x[2*BM + ml];
        #pragma unroll
        for (int wf = 0; wf < 2; ++wf) {
            #pragma unroll
            for (int j = 0; j < 4; ++j) {
                const int n = wf*32 + tn*4 + j;
                const float bv = B1[n];
                float4 cw = s_cw[n];
                float4 y4;
                y4.x = cw.w + cw.x*a.x + cw.y*c.x + cw.z*d.x;
                y4.y = cw.w + cw.x*a.y + cw.y*c.y + cw.z*d.y;
                y4.z = cw.w + cw.x*a.z + cw.y*c.z + cw.z*d.z;
                y4.w = cw.w + cw.x*a.w + cw.y*c.w + cw.z*d.w;
                float2 p0 = unpack2(acc[af][wf][j][0]);
                float2 p1 = unpack2(acc[af][wf][j][1]);
                float4 v;
                v.x = y4.x + 0.1f*(p0.x+bv);
                v.y = y4.y + 0.1f*(p0.y+bv);
                v.z = y4.z + 0.1f*(p1.x+bv);
                v.w = y4.w + 0.1f*(p1.y+bv);
                const size_t off = (size_t)(b*NF+n)*P0 + m;
                *(float4*)&OUT[off] = v;
                *(float4*)&EMB[off] = v;
            }
        }
    }
}

// ---------------- SGEMM: C[n][p] = sum_k A[k][p] * Wt[k][n] (+epilogue) ----------
// 256 threads, per-thread MT x 8N via fma.rn.f32x2. Up to 3 A-segments.
// EPI 0: C = lrelu(v+bias)
// EPI 1: C = O + clip(*leak)*(v+bias)
template<int BM, int BN, int EPI, int MT>
__global__ void __launch_bounds__(256, 1) k_gemm(
    const float* __restrict__ A1, int K1, long long sA1,
    const float* __restrict__ A2, int K2, long long sA2,
    const float* __restrict__ A3, int K3, long long sA3,
    const float* __restrict__ Wt, int ldw, long long sW,
    const float* __restrict__ bias, int sBias,
    float* __restrict__ C, long long sC,
    const float* __restrict__ O, const float* __restrict__ leak_ptr,
    int P, int tilesM)
{
    constexpr int BK  = 32;
    constexpr int TMC = BM/MT;
    constexpr int NA  = BK*BM/1024;
    constexpr int NW  = (BK*BN >= 1024) ? BK*BN/1024 : 1;

    extern __shared__ float smem[];
    float (*As)[BK][BM] = (float(*)[BK][BM])smem;
    float (*Ws)[BK][BN] = (float(*)[BK][BN])(smem + 2*BK*BM);

    const int b  = blockIdx.y;
    const int m0 = (blockIdx.x % tilesM) * BM;
    const int n0 = (blockIdx.x / tilesM) * BN;
    A1 += (size_t)b * sA1;
    if (A2) A2 += (size_t)b * sA2;
    if (A3) A3 += (size_t)b * sA3;
    Wt   += (size_t)b * sW;
    bias += (size_t)b * sBias;

    const int tid = threadIdx.x;
    const int tm = tid % TMC;
    const int tn = tid / TMC;

    constexpr int AF = MT/4;
    unsigned long long acc[AF][2][4][2];
    #pragma unroll
    for (int af = 0; af < AF; ++af)
        #pragma unroll
        for (int wf = 0; wf < 2; ++wf)
            #pragma unroll
            for (int j = 0; j < 4; ++j) { acc[af][wf][j][0] = 0ULL; acc[af][wf][j][1] = 0ULL; }

    const int K12 = K1 + K2;
    const int K = K12 + K3;
    const int T = K / BK;

    float4 pa[NA], pw[NW];
    auto prefetch = [&](int k0) {
        #pragma unroll
        for (int l = 0; l < NA; ++l) {
            int f  = tid + l*256;
            int kc = f / (BM/4);
            int mv = (f % (BM/4)) * 4;
            int kk = k0 + kc;
            int m  = m0 + mv;
            const float* src;
            if (kk < K1)      src = A1 + (size_t)kk*P;
            else if (kk < K12) src = A2 + (size_t)(kk-K1)*P;
            else               src = A3 + (size_t)(kk-K12)*P;
            pa[l] = (m < P) ? *(const float4*)(src + m) : make_float4(0.f,0.f,0.f,0.f);
        }
        #pragma unroll
        for (int l = 0; l < NW; ++l) {
            int f  = tid + l*256;
            int kc = f / (BN/4);
            int nv = (f % (BN/4)) * 4;
            pw[l] = *(const float4*)(Wt + (size_t)(k0+kc)*ldw + n0 + nv);
        }
    };
    auto store_tile = [&](int nb) {
        #pragma unroll
        for (int l = 0; l < NA; ++l) {
            int f  = tid + l*256;
            int kc = f / (BM/4);
            int mv = (f % (BM/4)) * 4;
            *(float4*)&As[nb][kc][mv] = pa[l];
        }
        #pragma unroll
        for (int l = 0; l < NW; ++l) {
            int f  = tid + l*256;
            int kc = f / (BN/4);
            int nv = (f % (BN/4)) * 4;
            *(float4*)&Ws[nb][kc][nv] = pw[l];
        }
    };

    prefetch(0);
    store_tile(0);
    __syncthreads();

    for (int t = 0; t < T; ++t) {
        const int buf = t & 1;
        if (t + 1 < T) prefetch((t + 1) * BK);
        #pragma unroll
        for (int kc = 0; kc < BK; ++kc) {
            ulonglong2 aA = *(const ulonglong2*)&As[buf][kc][tm*4];
            ulonglong2 aB;
            if (MT == 8) aB = *(const ulonglong2*)&As[buf][kc][BM/2 + tm*4];
            float4 wa = *(const float4*)&Ws[buf][kc][tn*4];
            float4 wb = *(const float4*)&Ws[buf][kc][BN/2 + tn*4];
            unsigned long long wd[2][4];
            wd[0][0] = pack2(wa.x, wa.x); wd[0][1] = pack2(wa.y, wa.y);
            wd[0][2] = pack2(wa.z, wa.z); wd[0][3] = pack2(wa.w, wa.w);
            wd[1][0] = pack2(wb.x, wb.x); wd[1][1] = pack2(wb.y, wb.y);
            wd[1][2] = pack2(wb.z, wb.z); wd[1][3] = pack2(wb.w, wb.w);
            #pragma unroll
            for (int wf = 0; wf < 2; ++wf)
                #pragma unroll
                for (int j = 0; j < 4; ++j) {
                    fma2(acc[0][wf][j][0], wd[wf][j], aA.x);
                    fma2(acc[0][wf][j][1], wd[wf][j], aA.y);
                    if (MT == 8) {
                        fma2(acc[AF-1][wf][j][0], wd[wf][j], aB.x);
                        fma2(acc[AF-1][wf][j][1], wd[wf][j], aB.y);
                    }
                }
        }
        if (t + 1 < T) store_tile(buf ^ 1);
        __syncthreads();
    }

    float lk = 0.1f;
    if (EPI == 1) { lk = *leak_ptr; lk = fminf(fmaxf(lk, 0.001f), 1000.f); }
    #pragma unroll
    for (int af = 0; af < AF; ++af) {
        const int m = m0 + (af ? BM/2 : 0) + tm*4;
        if (m >= P) continue;
        #pragma unroll
        for (int wf = 0; wf < 2; ++wf) {
            #pragma unroll
            for (int j = 0; j < 4; ++j) {
                const int n = n0 + (wf ? BN/2 : 0) + tn*4 + j;
                const float bv = bias[n];
                float2 p0 = unpack2(acc[af][wf][j][0]);
                float2 p1 = unpack2(acc[af][wf][j][1]);
                float4 v = make_float4(p0.x+bv, p0.y+bv, p1.x+bv, p1.y+bv);
                const size_t off = (size_t)b*sC + (size_t)n*P + m;
                if (EPI == 0) {
                    *(float4*)&C[off] = lrelu4(v);
                } else {
                    float4 o = *(const float4*)&O[off];
                    v.x = o.x + lk*v.x; v.y = o.y + lk*v.y;
                    v.z = o.z + lk*v.z; v.w = o.w + lk*v.w;
                    *(float4*)&C[off] = v;
                }
            }
        }
    }
}

// ---- fused downsample + next-iteration sobel ----
// down: gauss3x3(zero pad) + 2x2 mean on g_full[HxH] -> o[HnxHn] (g_out, emb)
// sobel: dx,dy of o (zero pad) -> g_perc, computed from the smem o-tile (+halo)
__global__ void k_downsobel(int H, int lgH, float* __restrict__ emb, int doSobel)
{
    const int Hn = H >> 1, lgHn = lgH - 1;
    const int Pn = Hn*Hn;
    const int tiles = (Hn + 15) >> 4;
    const int tileY = blockIdx.x / tiles, tileX = blockIdx.x % tiles;
    const int c = blockIdx.y & 63, b = blockIdx.y >> 6;
    __shared__ float s_o[18][18];
    const float* src = g_full + (size_t)(b*NF+c)*H*H;
    const float G0 = 0.27406861906119695f;
    const float G1 = 0.72593138093880305f;
    const float u4[4] = {G0, G1, G1, G0};
    const int tid = threadIdx.x;

    for (int e = tid; e < 324; e += 256) {
        const int hy = e / 18, hx = e % 18;
        const int oy = tileY*16 + hy - 1;
        const int ox = tileX*16 + hx - 1;
        float val = 0.f;
        if (oy >= 0 && oy < Hn && ox >= 0 && ox < Hn) {
            float acc = 0.f;
            #pragma unroll
            for (int r = 0; r < 4; ++r) {
                int yy = 2*oy + r - 1;
                if (yy < 0 || yy >= H) continue;
                float rowacc = 0.f;
                #pragma unroll
                for (int cc = 0; cc < 4; ++cc) {
                    int xx = 2*ox + cc - 1;
                    if (xx < 0 || xx >= H) continue;
                    rowacc += u4[cc]*src[(yy<<lgH)+xx];
                }
                acc += u4[r]*rowacc;
            }
            val = acc * 0.25f;
        }
        s_o[hy][hx] = val;
    }
    __syncthreads();

    const int ty = tid >> 4, tx = tid & 15;
    const int oy = tileY*16 + ty, ox = tileX*16 + tx;
    if (oy < Hn && ox < Hn) {
        const float o = s_o[ty+1][tx+1];
        const size_t idx = (size_t)(b*NF+c)*Pn + (oy<<lgHn) + ox;
        g_out[idx] = o;
        emb[idx]   = o;
        if (doSobel) {
            float m00 = s_o[ty  ][tx], m01 = s_o[ty  ][tx+1], m02 = s_o[ty  ][tx+2];
            float m10 = s_o[ty+1][tx],                         m12 = s_o[ty+1][tx+2];
            float m20 = s_o[ty+2][tx], m21 = s_o[ty+2][tx+1], m22 = s_o[ty+2][tx+2];
            float sx = (m00 - m02 + 2.f*(m10 - m12) + m20 - m22) * 0.125f;
            float sy = (m00 + 2.f*m01 + m02 - m20 - 2.f*m21 - m22) * 0.125f;
            float* dst = g_perc + (size_t)b*(2*NF)*Pn;
            dst[(size_t) c    *Pn + (oy<<lgHn) + ox] = sx;
            dst[(size_t)(NF+c)*Pn + (oy<<lgHn) + ox] = sy;
        }
    }
}

// ---------------- tail res_block at 2x2 + spatial mean -> g_hvec ----------------
__global__ void k_tail(const float* __restrict__ w0, const float* __restrict__ b0,
                       const float* __restrict__ w1, const float* __restrict__ b1)
{
    __shared__ float s_w0[NF*NF], s_w1[NF*NF], s_a[NF*4];
    const int o = threadIdx.x, b = blockIdx.x;
    for (int e = o; e < NF*NF; e += 64) {
        int r = e >> 6, i = e & 63;
        s_w0[(r<<6) | ((i + r) & 63)] = w0[e];
        s_w1[(r<<6) | ((i + r) & 63)] = w1[e];
    }
    const float bb0 = b0[o], bb1 = b1[o];
    __syncthreads();
    float v[4];
    #pragma unroll
    for (int py = 0; py < 4; ++py) v[py] = g_out[(size_t)(b*NF+o)*4 + py];
    *(float4*)&s_a[o*4] = make_float4(lrelu(v[0]),lrelu(v[1]),lrelu(v[2]),lrelu(v[3]));
    __syncthreads();
    float t[4] = {bb0,bb0,bb0,bb0};
    #pragma unroll
    for (int i = 0; i < NF; ++i) {
        float w = s_w0[(o<<6) | ((i + o) & 63)];
        float4 a = *(const float4*)&s_a[i*4];
        t[0] += w*a.x; t[1] += w*a.y; t[2] += w*a.z; t[3] += w*a.w;
    }
    __syncthreads();
    *(float4*)&s_a[o*4] = make_float4(lrelu(t[0]),lrelu(t[1]),lrelu(t[2]),lrelu(t[3]));
    __syncthreads();
    float u[4] = {bb1,bb1,bb1,bb1};
    #pragma unroll
    for (int i = 0; i < NF; ++i) {
        float w = s_w1[(o<<6) | ((i + o) & 63)];
        float4 a = *(const float4*)&s_a[i*4];
        u[0] += w*a.x; u[1] += w*a.y; u[2] += w*a.z; u[3] += w*a.w;
    }
    float m = 0.25f*((v[0]+0.1f*u[0]) + (v[1]+0.1f*u[1]) + (v[2]+0.1f*u[2]) + (v[3]+0.1f*u[3]));
    g_hvec[b*NF+o] = m;
}

// ---------------- latent head ----------------
__global__ void __launch_bounds__(512) k_head(
    const float* __restrict__ l1_sw, const float* __restrict__ l1_sb,
    const float* __restrict__ l1_w1, const float* __restrict__ l1_b1,
    const float* __restrict__ l1_w2, const float* __restrict__ l1_b2,
    const float* __restrict__ l2_w1, const float* __restrict__ l2_b1,
    const float* __restrict__ l2_w2, const float* __restrict__ l2_b2,
    const float* __restrict__ lo_w,  const float* __restrict__ lo_b,
    float* __restrict__ lat)
{
    __shared__ float s_h[NF], s_ha[NF];
    __shared__ float s_t[2*LATD];
    __shared__ float s_u[LATD];
    __shared__ float s_hh[LATD];
    const int j = threadIdx.x, b = blockIdx.x;
    if (j < NF) { float h = g_hvec[b*NF+j]; s_h[j] = h; s_ha[j] = lrelu(h); }
    __syncthreads();
    float xs = l1_sb[j];
    for (int i = 0; i < NF; ++i) xs += s_h[i]*l1_sw[i*LATD + j];
    float t0 = l1_b1[j], t1 = l1_b1[j+LATD];
    for (int i = 0; i < NF; ++i) {
        float a = s_ha[i];
        t0 += a*l1_w1[i*2*LATD + j];
        t1 += a*l1_w1[i*2*LATD + j + LATD];
    }
    s_t[j] = lrelu(t0); s_t[j+LATD] = lrelu(t1);
    __syncthreads();
    float v = l1_b2[j];
    for (int i = 0; i < 2*LATD; ++i) v += s_t[i]*l1_w2[(size_t)i*LATD + j];
    float hh = xs + 0.1f*v;
    s_hh[j] = hh; s_u[j] = lrelu(hh);
    __syncthreads();
    float t2 = l2_b1[j];
    for (int i = 0; i < LATD; ++i) t2 += s_u[i]*l2_w1[(size_t)i*LATD + j];
    __syncthreads();
    s_u[j] = lrelu(t2);
    __syncthreads();
    float v2 = l2_b2[j];
    for (int i = 0; i < LATD; ++i) v2 += s_u[i]*l2_w2[(size_t)i*LATD + j];
    float g = s_hh[j] + 0.1f*v2;
    s_t[j] = g;
    __syncthreads();
    float outv = lo_b[j];
    for (int i = 0; i < LATD; ++i) outv += s_t[i]*lo_w[(size_t)i*LATD + j];
    lat[b*LATD + j] = outv;
}

// ---------------- host launcher ----------------
extern "C" void kernel_launch(void* const* d_in, const int* in_sizes, int n_in,
                              void* d_out, int out_size)
{
    const float* x        = (const float*)d_in[0];
    const float* inj      = (const float*)d_in[1];
    const float* leak     = (const float*)d_in[2];
    const float* in_w     = (const float*)d_in[3];
    const float* in_b     = (const float*)d_in[4];
    const float* inrb_w0  = (const float*)d_in[5];
    const float* inrb_b0  = (const float*)d_in[6];
    const float* inrb_w1  = (const float*)d_in[7];
    const float* inrb_b1  = (const float*)d_in[8];
    const float* hyp_w    = (const float*)d_in[9];
    const float* hyp_b    = (const float*)d_in[10];
    const float* outrb_w0 = (const float*)d_in[11];
    const float* outrb_b0 = (const float*)d_in[12];
    const float* outrb_w1 = (const float*)d_in[13];
    const float* outrb_b1 = (const float*)d_in[14];
    const float* l1_sw    = (const float*)d_in[15];
    const float* l1_sb    = (const float*)d_in[16];
    const float* l1_w1    = (const float*)d_in[17];
    const float* l1_b1    = (const float*)d_in[18];
    const float* l1_w2    = (const float*)d_in[19];
    const float* l1_b2    = (const float*)d_in[20];
    const float* l2_w1    = (const float*)d_in[21];
    const float* l2_b1    = (const float*)d_in[22];
    const float* l2_w2    = (const float*)d_in[23];
    const float* l2_b2    = (const float*)d_in[24];
    const float* lo_w     = (const float*)d_in[25];
    const float* lo_b     = (const float*)d_in[26];
    float* out = (float*)d_out;

    float *p_perc, *p_h1, *p_h2, *p_full, *p_out, *p_wAT, *p_wMT, *p_wCDT, *p_bA, *p_bM, *p_bCD, *p_wRB;
    cudaGetSymbolAddress((void**)&p_perc, g_perc);
    cudaGetSymbolAddress((void**)&p_h1,   g_h1);
    cudaGetSymbolAddress((void**)&p_h2,   g_h2);
    cudaGetSymbolAddress((void**)&p_full, g_full);
    cudaGetSymbolAddress((void**)&p_out,  g_out);
    cudaGetSymbolAddress((void**)&p_wAT,  g_wAT);
    cudaGetSymbolAddress((void**)&p_wMT,  g_wMT);
    cudaGetSymbolAddress((void**)&p_wCDT, g_wCDT);
    cudaGetSymbolAddress((void**)&p_bA,   g_bA);
    cudaGetSymbolAddress((void**)&p_bM,   g_bM);
    cudaGetSymbolAddress((void**)&p_bCD,  g_bCD);
    cudaGetSymbolAddress((void**)&p_wRB,  g_wRB);

    // dynamic smem sizes (BK=32)
    const int SM_128_128 = (2*32*128 + 2*32*128) * 4;          // 64 KB
    const int SM_256_64  = (2*32*256 + 2*32*64)  * 4;          // 80 KB
    const int SM_128_64  = (2*32*128 + 2*32*64)  * 4;          // 48 KB
    const int SM_INRES   = SM_256_64 + (3*256 + 256) * 4;      // +4 KB x-tile/coeffs
    cudaFuncSetAttribute(k_inres,             cudaFuncAttributeMaxDynamicSharedMemorySize, SM_INRES);
    cudaFuncSetAttribute(k_gemm<256,64,1,8>,  cudaFuncAttributeMaxDynamicSharedMemorySize, SM_256_64);
    cudaFuncSetAttribute(k_gemm<128,128,0,8>, cudaFuncAttributeMaxDynamicSharedMemorySize, SM_128_128);
    cudaFuncSetAttribute(k_gemm<128,64,0,4>,  cudaFuncAttributeMaxDynamicSharedMemorySize, SM_128_64);
    cudaFuncSetAttribute(k_gemm<128,64,1,4>,  cudaFuncAttributeMaxDynamicSharedMemorySize, SM_128_64);

    float* emb0 = out + (size_t)BB*LATD;   // lat occupies [0, 4096)

    k_trw<<<32, 256>>>(inrb_w0, inrb_w1);
    k_hyper<<<dim3((PT/4 + 127)/128, 2), 128>>>(inj, hyp_w, hyp_b);
    // fused input conv + resblock -> g_out and emb0
    k_inres<<<dim3(P0/256, BB), 256, SM_INRES>>>(
        x, in_w, in_b, p_wRB, inrb_b0, inrb_b1, p_out, emb0);
    k_tr<<<dim3((61760 + 255)/256, BB), 256>>>();
    // initial sobel at H=128
    k_sobel4<<<(BB*NF*(P0/4) + 255)/256, 256>>>(128, 7);

    size_t off = (size_t)BB*LATD + (size_t)BB*NF*P0;
    int H = 128, lgH = 7;
    for (int it = 0; it < 6; ++it) {
        int P = H*H;
        if (P > 1024) {
            int tM = (P + 127)/128;
            k_gemm<128,128,0,8><<<dim3(tM, BB), 256, SM_128_128>>>(
                p_out, NF, (long long)NF*P, p_perc, 2*NF, (long long)2*NF*P,
                nullptr, 0, 0,
                p_wAT, FH, (long long)FIN*FH, p_bA, FH,
                p_h1, (long long)FH*P, nullptr, nullptr, P, tM);
            k_gemm<128,128,0,8><<<dim3(tM, BB), 256, SM_128_128>>>(
                p_h1, FH, (long long)FH*P, nullptr, 0, 0,
                nullptr, 0, 0,
                p_wMT, FH, (long long)FH*FH, p_bM, FH,
                p_h2, (long long)FH*P, nullptr, nullptr, P, tM);
            int tM2 = (P + 255)/256;
            k_gemm<256,64,1,8><<<dim3(tM2, BB), 256, SM_256_64>>>(
                p_h2, FH, (long long)FH*P, p_out, NF, (long long)NF*P,
                p_perc, 2*NF, (long long)2*NF*P,
                p_wCDT, NF, (long long)320*NF, p_bCD, NF,
                p_full, (long long)NF*P, p_out, leak, P, tM2);
        } else {
            int tM = (P + 127)/128;
            k_gemm<128,64,0,4><<<dim3(tM*2, BB), 256, SM_128_64>>>(
                p_out, NF, (long long)NF*P, p_perc, 2*NF, (long long)2*NF*P,
                nullptr, 0, 0,
                p_wAT, FH, (long long)FIN*FH, p_bA, FH,
                p_h1, (long long)FH*P, nullptr, nullptr, P, tM);
            k_gemm<128,64,0,4><<<dim3(tM*2, BB), 256, SM_128_64>>>(
                p_h1, FH, (long long)FH*P, nullptr, 0, 0,
                nullptr, 0, 0,
                p_wMT, FH, (long long)FH*FH, p_bM, FH,
                p_h2, (long long)FH*P, nullptr, nullptr, P, tM);
            k_gemm<128,64,1,4><<<dim3(tM, BB), 256, SM_128_64>>>(
                p_h2, FH, (long long)FH*P, p_out, NF, (long long)NF*P,
                p_perc, 2*NF, (long long)2*NF*P,
                p_wCDT, NF, (long long)320*NF, p_bCD, NF,
                p_full, (long long)NF*P, p_out, leak, P, tM);
        }
        int Hn = H/2;
        int tiles = (Hn + 15) >> 4;
        k_downsobel<<<dim3(tiles*tiles, NF*BB), 256>>>(H, lgH, out + off, it < 5 ? 1 : 0);
        off += (size_t)BB*NF*Hn*Hn;
        H = Hn; lgH -= 1;
    }
    k_tail<<<BB, 64>>>(outrb_w0, outrb_b0, outrb_w1, outrb_b1);
    k_head<<<BB, 512>>>(l1_sw, l1_sb, l1_w1, l1_b1, l1_w2, l1_b2,
                        l2_w1, l2_b1, l2_w2, l2_b2, lo_w, lo_b, out);
}

// round 15
// speedup vs baseline: 1.0257x; 1.0257x over previous
#include <cuda_runtime.h>
#include <cstddef>
#include <cstdint>

#define BB   8
#define NF   64
#define FIN  192
#define FH   128
#define LATD 512
#define PT   61824
#define P0   16384   // 128*128

// ---------------- scratch (device globals; no allocation) ----------------
__device__ float g_out [BB*NF *P0];
__device__ float g_perc[BB*2*NF*P0];  // dx,dy only (identity read from g_out)
__device__ float g_h1  [BB*FH *P0];
__device__ float g_h2  [BB*FH *P0];
__device__ float g_full[BB*NF *P0];
__device__ float g_dyn [BB*PT];
__device__ float g_wAT [BB*FIN*FH];   // [192][128] per sample (w_in^T)
__device__ float g_wMT [BB*FH*FH];    // [128][128] per sample (w_mid^T)
__device__ float g_wCDT[BB*320*NF];   // [320][64]: rows 0..127 w_out^T, 128..319 w_sk^T
__device__ float g_bA  [BB*FH];
__device__ float g_bM  [BB*FH];
__device__ float g_bCD [BB*NF];
__device__ float g_hvec[BB*NF];
__device__ float g_wRB [2*NF*NF];     // transposed inrb_w0, inrb_w1 (shared across batch)

__device__ __forceinline__ float lrelu(float x){ return x > 0.0f ? x : 0.2f*x; }
__device__ __forceinline__ float4 lrelu4(float4 v){
    return make_float4(lrelu(v.x), lrelu(v.y), lrelu(v.z), lrelu(v.w));
}
__device__ __forceinline__ void fma2(unsigned long long &d, unsigned long long a, unsigned long long b) {
    asm("fma.rn.f32x2 %0, %1, %2, %0;" : "+l"(d) : "l"(a), "l"(b));
}
__device__ __forceinline__ float2 unpack2(unsigned long long v) {
    float2 r; asm("mov.b64 {%0,%1}, %2;" : "=f"(r.x), "=f"(r.y) : "l"(v)); return r;
}
__device__ __forceinline__ unsigned long long pack2(float lo, float hi) {
    unsigned long long r; asm("mov.b64 %0, {%1,%2};" : "=l"(r) : "f"(lo), "f"(hi)); return r;
}

// ---------------- transpose static resblock weights ----------------
__global__ void k_trw(const float* __restrict__ w0, const float* __restrict__ w1)
{
    const int i = blockIdx.x*256 + threadIdx.x;   // 8192
    if (i < 4096) { int k = i >> 6, o = i & 63; g_wRB[i] = w0[o*64 + k]; }
    else { int j = i - 4096; int k = j >> 6, o = j & 63; g_wRB[i] = w1[o*64 + k]; }
}

// ------- hypernet: dyn = inj_lat @ hyp_w + hyp_b (float4, batch-split grid) -----
__global__ void k_hyper(const float* __restrict__ inj, const float* __restrict__ hw,
                        const float* __restrict__ hb)
{
    __shared__ float s_inj[4*LATD];
    const int tid = threadIdx.x;  // 128
    const int b0 = blockIdx.y * 4;
    for (int e = tid; e < 4*LATD; e += 128) s_inj[e] = inj[b0*LATD + e];
    __syncthreads();
    const int j4 = (blockIdx.x*128 + tid) * 4;
    if (j4 >= PT) return;
    float4 acc[4];
    #pragma unroll
    for (int b = 0; b < 4; ++b) acc[b] = make_float4(0.f,0.f,0.f,0.f);
    for (int k = 0; k < LATD; ++k) {
        float4 w = *(const float4*)&hw[(size_t)k*PT + j4];
        #pragma unroll
        for (int b = 0; b < 4; ++b) {
            float s = s_inj[b*LATD+k];
            acc[b].x += s*w.x; acc[b].y += s*w.y;
            acc[b].z += s*w.z; acc[b].w += s*w.w;
        }
    }
    float4 bb = *(const float4*)&hb[j4];
    #pragma unroll
    for (int b = 0; b < 4; ++b) {
        float4 r = make_float4(acc[b].x+bb.x, acc[b].y+bb.y, acc[b].z+bb.z, acc[b].w+bb.w);
        *(float4*)&g_dyn[(size_t)(b0+b)*PT + j4] = r;
    }
}

// ---------------- transpose dyn params into GEMM-friendly layout ----------------
__global__ void k_tr()
{
    const int b = blockIdx.y;
    int i = blockIdx.x*256 + threadIdx.x;
    const float* d = g_dyn + (size_t)b*PT;
    if (i < FIN*FH) { int k = i/FH, o = i%FH; g_wAT[(size_t)b*FIN*FH + i] = d[o*FIN + k]; return; }
    i -= FIN*FH;
    if (i < FH*FH)  { int k = i/FH, o = i%FH; g_wMT[(size_t)b*FH*FH + i] = d[24704 + o*FH + k]; return; }
    i -= FH*FH;
    if (i < 320*NF) { int k = i/NF, o = i%NF;
        g_wCDT[(size_t)b*320*NF + i] = (k < FH) ? d[41216 + o*FH + k]
                                                : d[49472 + o*FIN + (k-FH)];
        return; }
    i -= 320*NF;
    if (i < FH) { g_bA[b*FH+i] = d[24576+i]; return; }
    i -= FH;
    if (i < FH) { g_bM[b*FH+i] = d[41088+i]; return; }
    i -= FH;
    if (i < NF) { g_bCD[b*NF+i] = d[49408+i] + d[61760+i]; return; }
}

// ------- sin_sobel derivatives only: g_out -> g_perc [2NF ch], 4 px/thread -------
__global__ void k_sobel4(int H, int lgH)
{
    const int P = H*H;
    const int idx = blockIdx.x*256 + threadIdx.x;
    if (idx >= BB*NF*(P>>2)) return;
    const int q  = idx & ((P>>2)-1);
    const int c  = (idx >> (2*lgH-2)) & 63;
    const int b  = idx >> (2*lgH+4);
    const int p4 = q << 2;
    const int y  = p4 >> lgH, x0 = p4 & (H-1);
    const float* src = g_out + (size_t)(b*NF+c)*P;

    float am[6], ac[6], ap[6];
    {
        float4 v = *(const float4*)&src[p4];
        ac[0] = (x0 > 0)     ? src[p4-1] : 0.f;
        ac[1] = v.x; ac[2] = v.y; ac[3] = v.z; ac[4] = v.w;
        ac[5] = (x0+4 < H)   ? src[p4+4] : 0.f;
    }
    if (y > 0) {
        int base = (y-1) << lgH;
        float4 v = *(const float4*)&src[base + x0];
        am[0] = (x0 > 0)   ? src[base+x0-1] : 0.f;
        am[1] = v.x; am[2] = v.y; am[3] = v.z; am[4] = v.w;
        am[5] = (x0+4 < H) ? src[base+x0+4] : 0.f;
    } else { am[0]=am[1]=am[2]=am[3]=am[4]=am[5]=0.f; }
    if (y < H-1) {
        int base = (y+1) << lgH;
        float4 v = *(const float4*)&src[base + x0];
        ap[0] = (x0 > 0)   ? src[base+x0-1] : 0.f;
        ap[1] = v.x; ap[2] = v.y; ap[3] = v.z; ap[4] = v.w;
        ap[5] = (x0+4 < H) ? src[base+x0+4] : 0.f;
    } else { ap[0]=ap[1]=ap[2]=ap[3]=ap[4]=ap[5]=0.f; }

    float sx[4], sy[4];
    #pragma unroll
    for (int i = 0; i < 4; ++i) {
        float m00 = am[i], m01 = am[i+1], m02 = am[i+2];
        float m10 = ac[i],               m12 = ac[i+2];
        float m20 = ap[i], m21 = ap[i+1], m22 = ap[i+2];
        sx[i] = (m00 - m02 + 2.f*(m10 - m12) + m20 - m22) * 0.125f;
        sy[i] = (m00 + 2.f*m01 + m02 - m20 - 2.f*m21 - m22) * 0.125f;
    }
    float* dst = g_perc + (size_t)b*(2*NF)*P;
    *(float4*)&dst[(size_t) c    *P + p4] = make_float4(sx[0],sx[1],sx[2],sx[3]);
    *(float4*)&dst[(size_t)(NF+c)*P + p4] = make_float4(sy[0],sy[1],sy[2],sy[3]);
}

// ---- fused input path: y = conv1x1(x); out = y + 0.1*(lrelu(lrelu(y)@w0+b0)@w1+b1)
// BM=256, BN=64, K=64 twice; x tile and h1 tile live in smem; y recomputed in epilogue.
__global__ void __launch_bounds__(256, 1) k_inres(
    const float* __restrict__ X, const float* __restrict__ in_w,
    const float* __restrict__ in_b, const float* __restrict__ Wrb,
    const float* __restrict__ B0, const float* __restrict__ B1,
    float* __restrict__ OUT, float* __restrict__ EMB)
{
    constexpr int BM = 256, BN = 64, BK = 32, TMC = 32;
    extern __shared__ float smem[];
    float (*As)[BK][BM] = (float(*)[BK][BM])smem;                 // 64 KB
    float (*Ws)[BK][BN] = (float(*)[BK][BN])(smem + 2*BK*BM);     // 16 KB
    float* s_x  = smem + 2*BK*BM + 2*BK*BN;                       // 3*256 floats
    float4* s_cw = (float4*)(s_x + 3*BM);                         // 64 float4

    const int b  = blockIdx.y;
    const int m0 = blockIdx.x * BM;
    const float* xb = X + (size_t)b*3*P0 + m0;
    const int tid = threadIdx.x;
    const int tm = tid % TMC, tn = tid / TMC;

    if (tid < 192) {
        int ch = tid >> 6, i = tid & 63;
        *(float4*)&s_x[ch*BM + i*4] = *(const float4*)(xb + (size_t)ch*P0 + i*4);
    }
    if (tid < 64) s_cw[tid] = make_float4(in_w[tid*3], in_w[tid*3+1], in_w[tid*3+2], in_b[tid]);
    __syncthreads();

    #pragma unroll
    for (int l = 0; l < 16; ++l) {
        int f = tid + l*256;
        int kk = f >> 6;
        int mv = (f & 63) << 2;
        float4 cw = s_cw[kk];
        float4 a = *(const float4*)&s_x[mv];
        float4 c = *(const float4*)&s_x[BM + mv];
        float4 d = *(const float4*)&s_x[2*BM + mv];
        float4 y;
        y.x = cw.w + cw.x*a.x + cw.y*c.x + cw.z*d.x;
        y.y = cw.w + cw.x*a.y + cw.y*c.y + cw.z*d.y;
        y.z = cw.w + cw.x*a.z + cw.y*c.z + cw.z*d.z;
        y.w = cw.w + cw.x*a.w + cw.y*c.w + cw.z*d.w;
        *(float4*)&As[kk>>5][kk&31][mv] = lrelu4(y);
    }
    #pragma unroll
    for (int l = 0; l < 4; ++l) {
        int f = tid + l*256;
        int kk = f >> 4;
        int nv = (f & 15) << 2;
        *(float4*)&Ws[kk>>5][kk&31][nv] = *(const float4*)(Wrb + kk*BN + nv);
    }
    __syncthreads();

    unsigned long long acc[2][2][4][2];
    #pragma unroll
    for (int af=0; af<2; ++af)
        #pragma unroll
        for (int wf=0; wf<2; ++wf)
            #pragma unroll
            for (int j=0;j<4;++j){ acc[af][wf][j][0]=0ULL; acc[af][wf][j][1]=0ULL; }

    #pragma unroll
    for (int t = 0; t < 2; ++t)
        #pragma unroll
        for (int kc = 0; kc < BK; ++kc) {
            ulonglong2 aA = *(const ulonglong2*)&As[t][kc][tm*4];
            ulonglong2 aB = *(const ulonglong2*)&As[t][kc][128 + tm*4];
            float4 wa = *(const float4*)&Ws[t][kc][tn*4];
            float4 wb = *(const float4*)&Ws[t][kc][32 + tn*4];
            unsigned long long wd[2][4];
            wd[0][0]=pack2(wa.x,wa.x); wd[0][1]=pack2(wa.y,wa.y);
            wd[0][2]=pack2(wa.z,wa.z); wd[0][3]=pack2(wa.w,wa.w);
            wd[1][0]=pack2(wb.x,wb.x); wd[1][1]=pack2(wb.y,wb.y);
            wd[1][2]=pack2(wb.z,wb.z); wd[1][3]=pack2(wb.w,wb.w);
            #pragma unroll
            for (int wf = 0; wf < 2; ++wf)
                #pragma unroll
                for (int j = 0; j < 4; ++j) {
                    fma2(acc[0][wf][j][0], wd[wf][j], aA.x);
                    fma2(acc[0][wf][j][1], wd[wf][j], aA.y);
                    fma2(acc[1][wf][j][0], wd[wf][j], aB.x);
                    fma2(acc[1][wf][j][1], wd[wf][j], aB.y);
                }
        }
    __syncthreads();

    #pragma unroll
    for (int wf = 0; wf < 2; ++wf)
        #pragma unroll
        for (int j = 0; j < 4; ++j) {
            const int n = wf*32 + tn*4 + j;
            const float bv = B0[n];
            #pragma unroll
            for (int af = 0; af < 2; ++af) {
                float2 p0 = unpack2(acc[af][wf][j][0]);
                float2 p1 = unpack2(acc[af][wf][j][1]);
                *(float4*)&As[n>>5][n&31][af*128 + tm*4] =
                    make_float4(lrelu(p0.x+bv), lrelu(p0.y+bv),
                                lrelu(p1.x+bv), lrelu(p1.y+bv));
                acc[af][wf][j][0] = 0ULL; acc[af][wf][j][1] = 0ULL;
            }
        }
    #pragma unroll
    for (int l = 0; l < 4; ++l) {
        int f = tid + l*256;
        int kk = f >> 4;
        int nv = (f & 15) << 2;
        *(float4*)&Ws[kk>>5][kk&31][nv] = *(const float4*)(Wrb + NF*NF + kk*BN + nv);
    }
    __syncthreads();

    #pragma unroll
    for (int t = 0; t < 2; ++t)
        #pragma unroll
        for (int kc = 0; kc < BK; ++kc) {
            ulonglong2 aA = *(const ulonglong2*)&As[t][kc][tm*4];
            ulonglong2 aB = *(const ulonglong2*)&As[t][kc][128 + tm*4];
            float4 wa = *(const float4*)&Ws[t][kc][tn*4];
            float4 wb = *(const float4*)&Ws[t][kc][32 + tn*4];
            unsigned long long wd[2][4];
            wd[0][0]=pack2(wa.x,wa.x); wd[0][1]=pack2(wa.y,wa.y);
            wd[0][2]=pack2(wa.z,wa.z); wd[0][3]=pack2(wa.w,wa.w);
            wd[1][0]=pack2(wb.x,wb.x); wd[1][1]=pack2(wb.y,wb.y);
            wd[1][2]=pack2(wb.z,wb.z); wd[1][3]=pack2(wb.w,wb.w);
            #pragma unroll
            for (int wf = 0; wf < 2; ++wf)
                #pragma unroll
                for (int j = 0; j < 4; ++j) {
                    fma2(acc[0][wf][j][0], wd[wf][j], aA.x);
                    fma2(acc[0][wf][j][1], wd[wf][j], aA.y);
                    fma2(acc[1][wf][j][0], wd[wf][j], aB.x);
                    fma2(acc[1][wf][j][1], wd[wf][j], aB.y);
                }
        }

    #pragma unroll
    for (int af = 0; af < 2; ++af) {
        const int ml = af*128 + tm*4;
        const int m  = m0 + ml;
        float4 a = *(const float4*)&s_x[ml];
        float4 c = *(const float4*)&s_x[BM + ml];
        float4 d = *(const float4*)&s_x[2*BM + ml];
        #pragma unroll
        for (int wf = 0; wf < 2; ++wf) {
            #pragma unroll
            for (int j = 0; j < 4; ++j) {
                const int n = wf*32 + tn*4 + j;
                const float bv = B1[n];
                float4 cw = s_cw[n];
                float4 y4;
                y4.x = cw.w + cw.x*a.x + cw.y*c.x + cw.z*d.x;
                y4.y = cw.w + cw.x*a.y + cw.y*c.y + cw.z*d.y;
                y4.z = cw.w + cw.x*a.z + cw.y*c.z + cw.z*d.z;
                y4.w = cw.w + cw.x*a.w + cw.y*c.w + cw.z*d.w;
                float2 p0 = unpack2(acc[af][wf][j][0]);
                float2 p1 = unpack2(acc[af][wf][j][1]);
                float4 v;
                v.x = y4.x + 0.1f*(p0.x+bv);
                v.y = y4.y + 0.1f*(p0.y+bv);
                v.z = y4.z + 0.1f*(p1.x+bv);
                v.w = y4.w + 0.1f*(p1.y+bv);
                const size_t off = (size_t)(b*NF+n)*P0 + m;
                *(float4*)&OUT[off] = v;
                *(float4*)&EMB[off] = v;
            }
        }
    }
}

// ---------------- SGEMM: C[n][p] = sum_k A[k][p] * Wt[k][n] (+epilogue) ----------
// 256 threads, per-thread MT x 8N via fma.rn.f32x2. Up to 3 A-segments.
// EPI 0: C = lrelu(v+bias)
// EPI 1: C = O + clip(*leak)*(v+bias)
template<int BM, int BN, int EPI, int MT>
__global__ void __launch_bounds__(256, 1) k_gemm(
    const float* __restrict__ A1, int K1, long long sA1,
    const float* __restrict__ A2, int K2, long long sA2,
    const float* __restrict__ A3, int K3, long long sA3,
    const float* __restrict__ Wt, int ldw, long long sW,
    const float* __restrict__ bias, int sBias,
    float* __restrict__ C, long long sC,
    const float* __restrict__ O, const float* __restrict__ leak_ptr,
    int P, int tilesM)
{
    constexpr int BK  = 32;
    constexpr int TMC = BM/MT;
    constexpr int NA  = BK*BM/1024;
    constexpr int NW  = (BK*BN >= 1024) ? BK*BN/1024 : 1;

    extern __shared__ float smem[];
    float (*As)[BK][BM] = (float(*)[BK][BM])smem;
    float (*Ws)[BK][BN] = (float(*)[BK][BN])(smem + 2*BK*BM);

    const int b  = blockIdx.y;
    const int m0 = (blockIdx.x % tilesM) * BM;
    const int n0 = (blockIdx.x / tilesM) * BN;
    A1 += (size_t)b * sA1;
    if (A2) A2 += (size_t)b * sA2;
    if (A3) A3 += (size_t)b * sA3;
    Wt   += (size_t)b * sW;
    bias += (size_t)b * sBias;

    const int tid = threadIdx.x;
    const int tm = tid % TMC;
    const int tn = tid / TMC;

    constexpr int AF = MT/4;
    unsigned long long acc[AF][2][4][2];
    #pragma unroll
    for (int af = 0; af < AF; ++af)
        #pragma unroll
        for (int wf = 0; wf < 2; ++wf)
            #pragma unroll
            for (int j = 0; j < 4; ++j) { acc[af][wf][j][0] = 0ULL; acc[af][wf][j][1] = 0ULL; }

    const int K12 = K1 + K2;
    const int K = K12 + K3;
    const int T = K / BK;

    float4 pa[NA], pw[NW];
    auto prefetch = [&](int k0) {
        #pragma unroll
        for (int l = 0; l < NA; ++l) {
            int f  = tid + l*256;
            int kc = f / (BM/4);
            int mv = (f % (BM/4)) * 4;
            int kk = k0 + kc;
            int m  = m0 + mv;
            const float* src;
            if (kk < K1)      src = A1 + (size_t)kk*P;
            else if (kk < K12) src = A2 + (size_t)(kk-K1)*P;
            else               src = A3 + (size_t)(kk-K12)*P;
            pa[l] = (m < P) ? *(const float4*)(src + m) : make_float4(0.f,0.f,0.f,0.f);
        }
        #pragma unroll
        for (int l = 0; l < NW; ++l) {
            int f  = tid + l*256;
            int kc = f / (BN/4);
            int nv = (f % (BN/4)) * 4;
            pw[l] = *(const float4*)(Wt + (size_t)(k0+kc)*ldw + n0 + nv);
        }
    };
    auto store_tile = [&](int nb) {
        #pragma unroll
        for (int l = 0; l < NA; ++l) {
            int f  = tid + l*256;
            int kc = f / (BM/4);
            int mv = (f % (BM/4)) * 4;
            *(float4*)&As[nb][kc][mv] = pa[l];
        }
        #pragma unroll
        for (int l = 0; l < NW; ++l) {
            int f  = tid + l*256;
            int kc = f / (BN/4);
            int nv = (f % (BN/4)) * 4;
            *(float4*)&Ws[nb][kc][nv] = pw[l];
        }
    };

    prefetch(0);
    store_tile(0);
    __syncthreads();

    for (int t = 0; t < T; ++t) {
        const int buf = t & 1;
        if (t + 1 < T) prefetch((t + 1) * BK);
        #pragma unroll
        for (int kc = 0; kc < BK; ++kc) {
            ulonglong2 aA = *(const ulonglong2*)&As[buf][kc][tm*4];
            ulonglong2 aB;
            if (MT == 8) aB = *(const ulonglong2*)&As[buf][kc][BM/2 + tm*4];
            float4 wa = *(const float4*)&Ws[buf][kc][tn*4];
            float4 wb = *(const float4*)&Ws[buf][kc][BN/2 + tn*4];
            unsigned long long wd[2][4];
            wd[0][0] = pack2(wa.x, wa.x); wd[0][1] = pack2(wa.y, wa.y);
            wd[0][2] = pack2(wa.z, wa.z); wd[0][3] = pack2(wa.w, wa.w);
            wd[1][0] = pack2(wb.x, wb.x); wd[1][1] = pack2(wb.y, wb.y);
            wd[1][2] = pack2(wb.z, wb.z); wd[1][3] = pack2(wb.w, wb.w);
            #pragma unroll
            for (int wf = 0; wf < 2; ++wf)
                #pragma unroll
                for (int j = 0; j < 4; ++j) {
                    fma2(acc[0][wf][j][0], wd[wf][j], aA.x);
                    fma2(acc[0][wf][j][1], wd[wf][j], aA.y);
                    if (MT == 8) {
                        fma2(acc[AF-1][wf][j][0], wd[wf][j], aB.x);
                        fma2(acc[AF-1][wf][j][1], wd[wf][j], aB.y);
                    }
                }
        }
        if (t + 1 < T) store_tile(buf ^ 1);
        __syncthreads();
    }

    float lk = 0.1f;
    if (EPI == 1) { lk = *leak_ptr; lk = fminf(fmaxf(lk, 0.001f), 1000.f); }
    #pragma unroll
    for (int af = 0; af < AF; ++af) {
        const int m = m0 + (af ? BM/2 : 0) + tm*4;
        if (m >= P) continue;
        #pragma unroll
        for (int wf = 0; wf < 2; ++wf) {
            #pragma unroll
            for (int j = 0; j < 4; ++j) {
                const int n = n0 + (wf ? BN/2 : 0) + tn*4 + j;
                const float bv = bias[n];
                float2 p0 = unpack2(acc[af][wf][j][0]);
                float2 p1 = unpack2(acc[af][wf][j][1]);
                float4 v = make_float4(p0.x+bv, p0.y+bv, p1.x+bv, p1.y+bv);
                const size_t off = (size_t)b*sC + (size_t)n*P + m;
                if (EPI == 0) {
                    *(float4*)&C[off] = lrelu4(v);
                } else {
                    float4 o = *(const float4*)&O[off];
                    v.x = o.x + lk*v.x; v.y = o.y + lk*v.y;
                    v.z = o.z + lk*v.z; v.w = o.w + lk*v.w;
                    *(float4*)&C[off] = v;
                }
            }
        }
    }
}

// ---------------- gauss 3x3 (zero pad) + 2x2 mean, writes g_out + emb ----------------
__global__ void k_down(int H, int lgH, float* __restrict__ emb)
{
    const int Hn = H >> 1, Pn = Hn*Hn;
    const int lgHn = lgH - 1;
    const int idx = blockIdx.x*256 + threadIdx.x;
    if (idx >= BB*NF*Pn) return;
    const int p = idx & (Pn-1);
    const int c = (idx >> (2*lgHn)) & (NF-1);
    const int b = idx >> (2*lgHn + 6);
    const int oy = p >> lgHn, ox = p & (Hn-1);
    const float* src = g_full + (size_t)(b*NF+c)*H*H;
    const float G0 = 0.27406861906119695f;
    const float G1 = 0.72593138093880305f;
    const float u4[4] = {G0, G1, G1, G0};
    float acc = 0.f;
    #pragma unroll
    for (int r = 0; r < 4; ++r) {
        int yy = 2*oy + r - 1;
        if (yy < 0 || yy >= H) continue;
        float rowacc = 0.f;
        #pragma unroll
        for (int cc = 0; cc < 4; ++cc) {
            int xx = 2*ox + cc - 1;
            if (xx < 0 || xx >= H) continue;
            rowacc += u4[cc]*src[(yy<<lgH)+xx];
        }
        acc += u4[r]*rowacc;
    }
    acc *= 0.25f;
    const size_t o = (size_t)(b*NF+c)*Pn + p;
    g_out[o] = acc;
    emb[o]   = acc;
}

// ---------------- tail res_block at 2x2 + spatial mean -> g_hvec ----------------
__global__ void k_tail(const float* __restrict__ w0, const float* __restrict__ b0,
                       const float* __restrict__ w1, const float* __restrict__ b1)
{
    __shared__ float s_w0[NF*NF], s_w1[NF*NF], s_a[NF*4];
    const int o = threadIdx.x, b = blockIdx.x;
    for (int e = o; e < NF*NF; e += 64) {
        int r = e >> 6, i = e & 63;
        s_w0[(r<<6) | ((i + r) & 63)] = w0[e];
        s_w1[(r<<6) | ((i + r) & 63)] = w1[e];
    }
    const float bb0 = b0[o], bb1 = b1[o];
    __syncthreads();
    float v[4];
    #pragma unroll
    for (int py = 0; py < 4; ++py) v[py] = g_out[(size_t)(b*NF+o)*4 + py];
    *(float4*)&s_a[o*4] = make_float4(lrelu(v[0]),lrelu(v[1]),lrelu(v[2]),lrelu(v[3]));
    __syncthreads();
    float t[4] = {bb0,bb0,bb0,bb0};
    #pragma unroll
    for (int i = 0; i < NF; ++i) {
        float w = s_w0[(o<<6) | ((i + o) & 63)];
        float4 a = *(const float4*)&s_a[i*4];
        t[0] += w*a.x; t[1] += w*a.y; t[2] += w*a.z; t[3] += w*a.w;
    }
    __syncthreads();
    *(float4*)&s_a[o*4] = make_float4(lrelu(t[0]),lrelu(t[1]),lrelu(t[2]),lrelu(t[3]));
    __syncthreads();
    float u[4] = {bb1,bb1,bb1,bb1};
    #pragma unroll
    for (int i = 0; i < NF; ++i) {
        float w = s_w1[(o<<6) | ((i + o) & 63)];
        float4 a = *(const float4*)&s_a[i*4];
        u[0] += w*a.x; u[1] += w*a.y; u[2] += w*a.z; u[3] += w*a.w;
    }
    float m = 0.25f*((v[0]+0.1f*u[0]) + (v[1]+0.1f*u[1]) + (v[2]+0.1f*u[2]) + (v[3]+0.1f*u[3]));
    g_hvec[b*NF+o] = m;
}

// ---------------- latent head ----------------
__global__ void __launch_bounds__(512) k_head(
    const float* __restrict__ l1_sw, const float* __restrict__ l1_sb,
    const float* __restrict__ l1_w1, const float* __restrict__ l1_b1,
    const float* __restrict__ l1_w2, const float* __restrict__ l1_b2,
    const float* __restrict__ l2_w1, const float* __restrict__ l2_b1,
    const float* __restrict__ l2_w2, const float* __restrict__ l2_b2,
    const float* __restrict__ lo_w,  const float* __restrict__ lo_b,
    float* __restrict__ lat)
{
    __shared__ float s_h[NF], s_ha[NF];
    __shared__ float s_t[2*LATD];
    __shared__ float s_u[LATD];
    __shared__ float s_hh[LATD];
    const int j = threadIdx.x, b = blockIdx.x;
    if (j < NF) { float h = g_hvec[b*NF+j]; s_h[j] = h; s_ha[j] = lrelu(h); }
    __syncthreads();
    float xs = l1_sb[j];
    for (int i = 0; i < NF; ++i) xs += s_h[i]*l1_sw[i*LATD + j];
    float t0 = l1_b1[j], t1 = l1_b1[j+LATD];
    for (int i = 0; i < NF; ++i) {
        float a = s_ha[i];
        t0 += a*l1_w1[i*2*LATD + j];
        t1 += a*l1_w1[i*2*LATD + j + LATD];
    }
    s_t[j] = lrelu(t0); s_t[j+LATD] = lrelu(t1);
    __syncthreads();
    float v = l1_b2[j];
    for (int i = 0; i < 2*LATD; ++i) v += s_t[i]*l1_w2[(size_t)i*LATD + j];
    float hh = xs + 0.1f*v;
    s_hh[j] = hh; s_u[j] = lrelu(hh);
    __syncthreads();
    float t2 = l2_b1[j];
    for (int i = 0; i < LATD; ++i) t2 += s_u[i]*l2_w1[(size_t)i*LATD + j];
    __syncthreads();
    s_u[j] = lrelu(t2);
    __syncthreads();
    float v2 = l2_b2[j];
    for (int i = 0; i < LATD; ++i) v2 += s_u[i]*l2_w2[(size_t)i*LATD + j];
    float g = s_hh[j] + 0.1f*v2;
    s_t[j] = g;
    __syncthreads();
    float outv = lo_b[j];
    for (int i = 0; i < LATD; ++i) outv += s_t[i]*lo_w[(size_t)i*LATD + j];
    lat[b*LATD + j] = outv;
}

// ---------------- host launcher ----------------
extern "C" void kernel_launch(void* const* d_in, const int* in_sizes, int n_in,
                              void* d_out, int out_size)
{
    const float* x        = (const float*)d_in[0];
    const float* inj      = (const float*)d_in[1];
    const float* leak     = (const float*)d_in[2];
    const float* in_w     = (const float*)d_in[3];
    const float* in_b     = (const float*)d_in[4];
    const float* inrb_w0  = (const float*)d_in[5];
    const float* inrb_b0  = (const float*)d_in[6];
    const float* inrb_w1  = (const float*)d_in[7];
    const float* inrb_b1  = (const float*)d_in[8];
    const float* hyp_w    = (const float*)d_in[9];
    const float* hyp_b    = (const float*)d_in[10];
    const float* outrb_w0 = (const float*)d_in[11];
    const float* outrb_b0 = (const float*)d_in[12];
    const float* outrb_w1 = (const float*)d_in[13];
    const float* outrb_b1 = (const float*)d_in[14];
    const float* l1_sw    = (const float*)d_in[15];
    const float* l1_sb    = (const float*)d_in[16];
    const float* l1_w1    = (const float*)d_in[17];
    const float* l1_b1    = (const float*)d_in[18];
    const float* l1_w2    = (const float*)d_in[19];
    const float* l1_b2    = (const float*)d_in[20];
    const float* l2_w1    = (const float*)d_in[21];
    const float* l2_b1    = (const float*)d_in[22];
    const float* l2_w2    = (const float*)d_in[23];
    const float* l2_b2    = (const float*)d_in[24];
    const float* lo_w     = (const float*)d_in[25];
    const float* lo_b     = (const float*)d_in[26];
    float* out = (float*)d_out;

    float *p_perc, *p_h1, *p_h2, *p_full, *p_out, *p_wAT, *p_wMT, *p_wCDT, *p_bA, *p_bM, *p_bCD, *p_wRB;
    cudaGetSymbolAddress((void**)&p_perc, g_perc);
    cudaGetSymbolAddress((void**)&p_h1,   g_h1);
    cudaGetSymbolAddress((void**)&p_h2,   g_h2);
    cudaGetSymbolAddress((void**)&p_full, g_full);
    cudaGetSymbolAddress((void**)&p_out,  g_out);
    cudaGetSymbolAddress((void**)&p_wAT,  g_wAT);
    cudaGetSymbolAddress((void**)&p_wMT,  g_wMT);
    cudaGetSymbolAddress((void**)&p_wCDT, g_wCDT);
    cudaGetSymbolAddress((void**)&p_bA,   g_bA);
    cudaGetSymbolAddress((void**)&p_bM,   g_bM);
    cudaGetSymbolAddress((void**)&p_bCD,  g_bCD);
    cudaGetSymbolAddress((void**)&p_wRB,  g_wRB);

    // dynamic smem sizes (BK=32)
    const int SM_128_128 = (2*32*128 + 2*32*128) * 4;          // 64 KB
    const int SM_256_64  = (2*32*256 + 2*32*64)  * 4;          // 80 KB
    const int SM_128_64  = (2*32*128 + 2*32*64)  * 4;          // 48 KB
    const int SM_INRES   = SM_256_64 + (3*256 + 256) * 4;      // +4 KB x-tile/coeffs
    cudaFuncSetAttribute(k_inres,             cudaFuncAttributeMaxDynamicSharedMemorySize, SM_INRES);
    cudaFuncSetAttribute(k_gemm<256,64,1,8>,  cudaFuncAttributeMaxDynamicSharedMemorySize, SM_256_64);
    cudaFuncSetAttribute(k_gemm<128,128,0,8>, cudaFuncAttributeMaxDynamicSharedMemorySize, SM_128_128);
    cudaFuncSetAttribute(k_gemm<128,64,0,4>,  cudaFuncAttributeMaxDynamicSharedMemorySize, SM_128_64);
    cudaFuncSetAttribute(k_gemm<128,64,1,4>,  cudaFuncAttributeMaxDynamicSharedMemorySize, SM_128_64);

    float* emb0 = out + (size_t)BB*LATD;   // lat occupies [0, 4096)

    k_trw<<<32, 256>>>(inrb_w0, inrb_w1);
    k_hyper<<<dim3((PT/4 + 127)/128, 2), 128>>>(inj, hyp_w, hyp_b);
    // fused input conv + resblock -> g_out and emb0
    k_inres<<<dim3(P0/256, BB), 256, SM_INRES>>>(
        x, in_w, in_b, p_wRB, inrb_b0, inrb_b1, p_out, emb0);
    k_tr<<<dim3((61760 + 255)/256, BB), 256>>>();

    size_t off = (size_t)BB*LATD + (size_t)BB*NF*P0;
    int H = 128, lgH = 7;
    for (int it = 0; it < 6; ++it) {
        int P = H*H;
        k_sobel4<<<(BB*NF*(P/4) + 255)/256, 256>>>(H, lgH);
        if (P > 1024) {
            int tM = (P + 127)/128;
            k_gemm<128,128,0,8><<<dim3(tM, BB), 256, SM_128_128>>>(
                p_out, NF, (long long)NF*P, p_perc, 2*NF, (long long)2*NF*P,
                nullptr, 0, 0,
                p_wAT, FH, (long long)FIN*FH, p_bA, FH,
                p_h1, (long long)FH*P, nullptr, nullptr, P, tM);
            k_gemm<128,128,0,8><<<dim3(tM, BB), 256, SM_128_128>>>(
                p_h1, FH, (long long)FH*P, nullptr, 0, 0,
                nullptr, 0, 0,
                p_wMT, FH, (long long)FH*FH, p_bM, FH,
                p_h2, (long long)FH*P, nullptr, nullptr, P, tM);
            int tM2 = (P + 255)/256;
            k_gemm<256,64,1,8><<<dim3(tM2, BB), 256, SM_256_64>>>(
                p_h2, FH, (long long)FH*P, p_out, NF, (long long)NF*P,
                p_perc, 2*NF, (long long)2*NF*P,
                p_wCDT, NF, (long long)320*NF, p_bCD, NF,
                p_full, (long long)NF*P, p_out, leak, P, tM2);
        } else {
            int tM = (P + 127)/128;
            k_gemm<128,64,0,4><<<dim3(tM*2, BB), 256, SM_128_64>>>(
                p_out, NF, (long long)NF*P, p_perc, 2*NF, (long long)2*NF*P,
                nullptr, 0, 0,
                p_wAT, FH, (long long)FIN*FH, p_bA, FH,
                p_h1, (long long)FH*P, nullptr, nullptr, P, tM);
            k_gemm<128,64,0,4><<<dim3(tM*2, BB), 256, SM_128_64>>>(
                p_h1, FH, (long long)FH*P, nullptr, 0, 0,
                nullptr, 0, 0,
                p_wMT, FH, (long long)FH*FH, p_bM, FH,
                p_h2, (long long)FH*P, nullptr, nullptr, P, tM);
            k_gemm<128,64,1,4><<<dim3(tM, BB), 256, SM_128_64>>>(
                p_h2, FH, (long long)FH*P, p_out, NF, (long long)NF*P,
                p_perc, 2*NF, (long long)2*NF*P,
                p_wCDT, NF, (long long)320*NF, p_bCD, NF,
                p_full, (long long)NF*P, p_out, leak, P, tM);
        }
        int Hn = H/2, Pn = Hn*Hn;
        k_down<<<(BB*NF*Pn + 255)/256, 256>>>(H, lgH, out + off);
        off += (size_t)BB*NF*Pn;
        H = Hn; lgH -= 1;
    }
    k_tail<<<BB, 64>>>(outrb_w0, outrb_b0, outrb_w1, outrb_b1);
    k_head<<<BB, 512>>>(l1_sw, l1_sb, l1_w1, l1_b1, l1_w2, l1_b2,
                        l2_w1, l2_b1, l2_w2, l2_b2, lo_w, lo_b, out);
}